// round 10
// baseline (speedup 1.0000x reference)
#include <cuda_runtime.h>
#include <stdint.h>
#include <limits.h>

// Problem scale (dataset fixed: T=2048, W=30, N=61440, k=819)
#define NMAX  61440
#define TMAX  2048
#define NB    60          // radix blocks; NB*CHUNK >= NMAX
#define CHUNK 1024
#define NT    1024

#define ST_UND 0
#define ST_ACC 1
#define ST_REJ 2

// ---- device-global scratch (no allocations allowed) ----
__device__ unsigned long long g_bufA[NMAX];
__device__ unsigned long long g_bufB[NMAX];
__device__ unsigned int       g_hist4[4][256 * NB];

__device__ __forceinline__ bool spans_cross(int s1, int e1, int s2, int e2) {
    return (s1 < s2 && s2 <= e1 && e1 < e2) || (s2 < s1 && s1 <= e2 && e2 < e1);
}

// ============================================================
// Kernel 1: keys + pass-0 histogram + zero later-pass histograms.
// key64 = (~sortable_asc(score+log m)) << 32 | idx
// ============================================================
__global__ void __launch_bounds__(CHUNK, 1)
k_init_hist(const float* __restrict__ scores, const float* __restrict__ maskp, int N) {
    __shared__ unsigned h[256];
    int t = threadIdx.x, ln = t & 31;
    unsigned ltm = (1u << ln) - 1u;
    if (t < 256) h[t] = 0;
    __syncthreads();

    int i = blockIdx.x * CHUNK + t;
    bool ok = (i < N);
    unsigned d = 256u + (unsigned)ln;
    if (ok) {
        float key = scores[i] + logf(maskp[i]);
        unsigned b   = __float_as_uint(key);
        unsigned asc = (b & 0x80000000u) ? ~b : (b | 0x80000000u);
        unsigned long long k = ((unsigned long long)(~asc) << 32) | (unsigned)i;
        g_bufA[i] = k;
        d = (unsigned)((k >> 32) & 255u);
    }
    unsigned mm = __match_any_sync(0xFFFFFFFFu, d);
    if (ok && (mm & ltm) == 0u) atomicAdd(&h[d], (unsigned)__popc(mm));
    __syncthreads();

    if (t < 256) {
        g_hist4[0][t * NB + blockIdx.x] = h[t];
        g_hist4[1][t * NB + blockIdx.x] = 0;
        g_hist4[2][t * NB + blockIdx.x] = 0;
        g_hist4[3][t * NB + blockIdx.x] = 0;
    }
}

// ============================================================
// Scatter pass p: 1024 threads, ONE wave per block.
// Inline bases from g_hist4[p]; stable scatter; feed next pass hist (p<3).
// ============================================================
__global__ void __launch_bounds__(1024, 1)
k_scatter(int p, int srcIsA, int N) {
    const unsigned long long* src = srcIsA ? g_bufA : g_bufB;
    unsigned long long*       dst = srcIsA ? g_bufB : g_bufA;
    int shift  = 32 + 8 * p;
    int shift2 = shift + 8;

    __shared__ unsigned base[256];
    __shared__ unsigned wh[32][257];   // padded: column scan hits rotating banks
    __shared__ unsigned tmp8[8];
    int t  = threadIdx.x;
    int wp = t >> 5, ln = t & 31;
    unsigned ltm = (1u << ln) - 1u;
    const unsigned FULL = 0xFFFFFFFFu;

    // zero per-warp counts (done by everyone while t<256 also compute bases)
    #pragma unroll
    for (int j = t; j < 32 * 257; j += 1024) ((unsigned*)wh)[j] = 0;

    if (t < 256) {
        // per-digit: global base = scan(totals) + prefix over earlier blocks
        unsigned pre = 0, tot = 0;
        const unsigned* hp = &g_hist4[p][t * NB];
        int myb = blockIdx.x;
        #pragma unroll
        for (int b = 0; b < NB; b++) {
            unsigned c = __ldg(&hp[b]);
            pre += (b < myb) ? c : 0u;
            tot += c;
        }
        unsigned x = tot;
        #pragma unroll
        for (int o = 1; o < 32; o <<= 1) {
            unsigned y = __shfl_up_sync(FULL, x, o);
            if (ln >= o) x += y;
        }
        if (ln == 31) tmp8[wp] = x;
        __syncwarp();
        base[t] = (x - tot) + pre;     // warp-level part; add tmp8 prefix below
    }
    __syncthreads();
    if (t < 256) {
        unsigned add = 0;
        #pragma unroll
        for (int w = 0; w < 8; w++) add += (w < wp) ? tmp8[w] : 0u;
        base[t] += add;
    }

    // one wave: rank + scatter
    int i = blockIdx.x * 1024 + t;
    bool ok = (i < N);
    unsigned long long v = ok ? src[i] : 0ull;
    unsigned d = ok ? (unsigned)((v >> shift) & 255u) : (256u + (unsigned)ln);
    unsigned mm = __match_any_sync(FULL, d);
    int lr = __popc(mm & ltm);
    if (ok && lr == 0) wh[wp][d] = (unsigned)__popc(mm);
    __syncthreads();

    // thread t<256 owns digit t: exclusive prefix across 32 warps
    if (t < 256) {
        unsigned run = base[t];
        #pragma unroll
        for (int w = 0; w < 32; w++) { unsigned c = wh[w][t]; wh[w][t] = run; run += c; }
    }
    __syncthreads();

    if (ok) {
        unsigned q = wh[wp][d] + (unsigned)lr;
        dst[q] = v;                                  // stable scatter
        if (p < 3) {
            unsigned d2 = (unsigned)((v >> shift2) & 255u);
            atomicAdd(&g_hist4[p + 1][d2 * NB + (q >> 10)], 1u);
        }
    }
}

// ============================================================
// Greedy non-crossing selection: block-parallel fixed-point per chunk.
//   Prefilter: width-0 -> ACC immediately; reject vs cross-chunk tables (final).
//   Rounds with resume-from-first-blocker; bucket locality (|ds|<=29 -> 3 buckets).
// Finalize: first K accepts (candidate order), bitonic by (s*T+e, idx), emit.
// ============================================================
__global__ void __launch_bounds__(NT, 1)
k_greedy(const int* __restrict__ spans, const float* __restrict__ scores,
         const int* __restrict__ pT, const int* __restrict__ pK,
         int N, float* __restrict__ out, int out_size) {
    __shared__ int s2e[TMAX];                 // start -> max end   (-1 unset)
    __shared__ int e2s[TMAX];                 // end   -> min start (INT_MAX unset)
    __shared__ int seC[NT];                   // packed (s<<12|e)
    __shared__ int cC[NT];                    // candidate id
    __shared__ int stateA[NT];
    __shared__ short bEntries[NT];
    __shared__ int bCnt[64], bOff[64], bFill[64];
    __shared__ int wCnt[32], wOff[32];
    __shared__ unsigned long long accList[2048];
    __shared__ int sh_cnt, sh_done;

    const unsigned FULL = 0xFFFFFFFFu;
    int t = threadIdx.x, wp = t >> 5, ln = t & 31;
    unsigned ltm = (1u << ln) - 1u;

    for (int i = t; i < TMAX; i += NT) { s2e[i] = -1; e2s[i] = INT_MAX; }
    if (t == 0) { sh_cnt = 0; sh_done = 0; }
    __syncthreads();

    int T = pT ? pT[0] : TMAX;
    int K = pK ? pK[0] : 819;
    int k_out = out_size / 5;                  // scores,k | idx,k | spans,2k | valid,k
    if (K > NT) K = NT;
    int nch = (N + NT - 1) / NT;

    for (int ch = 0; ch < nch; ch++) {
        if (sh_done) break;
        int cnt0 = sh_cnt;
        int i = ch * NT + t;
        int myState = ST_REJ;
        int s1 = 0, e1 = 0, c1 = 0;
        if (i < N) {
            c1 = (int)(unsigned)(g_bufA[i] & 0xFFFFFFFFull);
            s1 = __ldg(&spans[2 * c1]);
            e1 = __ldg(&spans[2 * c1 + 1]);
            if (s1 == e1) {
                myState = ST_ACC;              // width-0: can never cross
            } else if (cnt0 == 0) {
                myState = ST_UND;
            } else {
                bool cross = false;
                int w = e1 - s1;
                for (int d = 1; d <= w; d++) cross |= (s2e[s1 + d] > e1);
                for (int d = 0; d < w; d++)  cross |= (e2s[s1 + d] < s1);
                myState = cross ? ST_REJ : ST_UND;
            }
        }
        seC[t] = (s1 << 12) | e1;
        cC[t]  = c1;
        stateA[t] = myState;
        int myB = s1 >> 5;

        // ---- bucket build over UND only ----
        if (t < 64) bCnt[t] = 0;
        __syncthreads();
        if (myState == ST_UND) atomicAdd(&bCnt[myB], 1);
        __syncthreads();
        if (t == 0) {
            int run = 0;
            #pragma unroll
            for (int b = 0; b < 64; b++) { bOff[b] = run; bFill[b] = run; run += bCnt[b]; }
        }
        __syncthreads();
        if (myState == ST_UND) {
            int pos = atomicAdd(&bFill[myB], 1);
            bEntries[pos] = (short)t;
        }
        __syncthreads();

        // scan interval: buckets myB-1..myB+1 are contiguous in bEntries
        int bLo = (myB > 0) ? myB - 1 : 0;
        int bHi = (myB < 63) ? myB + 1 : 63;
        int fb = bOff[bLo];
        int hi = bOff[bHi] + bCnt[bHi];

        // ---- rounds with resume-from-first-blocker ----
        while (true) {
            int und = __syncthreads_count(myState == ST_UND);
            if (und == 0) break;
            if (myState == ST_UND) {
                bool rejected = false, blocked = false;
                int q = fb;
                for (; q < hi; q++) {
                    int j = bEntries[q];
                    if (j >= t) continue;
                    int st = stateA[j];
                    if (st == ST_REJ) continue;
                    int se2 = seC[j];
                    if (spans_cross(s1, e1, se2 >> 12, se2 & 4095)) {
                        if (st == ST_ACC) { rejected = true; break; }
                        blocked = true; fb = q; break;   // resume here next round
                    }
                }
                if (rejected)      { myState = ST_REJ; stateA[t] = ST_REJ; }
                else if (!blocked) { myState = ST_ACC; stateA[t] = ST_ACC; }
            }
        }

        // ---- accepted: update tables for later chunks ----
        bool accd = (myState == ST_ACC);
        if (accd) {
            atomicMax(&s2e[s1], e1);
            atomicMin(&e2s[e1], s1);
        }

        // ---- ordered compaction of accepts -> accList ----
        unsigned bal = __ballot_sync(FULL, accd);
        if (ln == 0) wCnt[wp] = __popc(bal);
        __syncthreads();
        if (t < 32) {
            int vv = wCnt[t], a2 = vv;
            #pragma unroll
            for (int o = 1; o < 32; o <<= 1) {
                int nb = __shfl_up_sync(FULL, a2, o);
                if (t >= o) a2 += nb;
            }
            wOff[t] = a2 - vv;
            if (t == 31) {
                sh_cnt = cnt0 + a2;
                if (cnt0 + a2 >= K) sh_done = 1;
            }
        }
        __syncthreads();
        if (accd) {
            int pos = cnt0 + wOff[wp] + __popc(bal & ltm);
            if (pos < 2048)
                accList[pos] = ((unsigned long long)(s1 * T + e1) << 17) | (unsigned)c1;
        }
        __syncthreads();
    }

    // ---- finalize: first K accepts, bitonic by (s*T+e, idx), emit ----
    int cnt = sh_cnt;
    if (cnt > K) cnt = K;
    if (t >= cnt) accList[t] = 0xFFFFFFFFFFFFFFFFull;
    __syncthreads();

    for (int ks = 2; ks <= NT; ks <<= 1) {
        for (int j = ks >> 1; j > 0; j >>= 1) {
            int ixj = t ^ j;
            if (ixj > t) {
                bool up = ((t & ks) == 0);
                unsigned long long a = accList[t], b = accList[ixj];
                if ((a > b) == up) { accList[t] = b; accList[ixj] = a; }
            }
            __syncthreads();
        }
    }

    int vcnt = (cnt < k_out) ? cnt : k_out;
    for (int j = t; j < k_out; j += NT) {
        bool valid = (j < vcnt);
        int c  = valid ? (int)(accList[j] & 0x1FFFFull) : 0;
        float sc = valid ? scores[c] : 0.0f;
        int ss = valid ? spans[2 * c] : 0;
        int ee = valid ? spans[2 * c + 1] : 0;
        out[j]                     = sc;
        out[k_out + j]             = valid ? (float)c : 0.0f;
        out[2 * k_out + 2 * j]     = (float)ss;
        out[2 * k_out + 2 * j + 1] = (float)ee;
        out[4 * k_out + j]         = valid ? 1.0f : 0.0f;
    }
}

// ============================================================
// Launch: 6 nodes.
// ============================================================
extern "C" void kernel_launch(void* const* d_in, const int* in_sizes, int n_in,
                              void* d_out, int out_size) {
    const int*   spans  = (const int*)d_in[0];
    const float* scores = (const float*)d_in[1];
    const float* mask   = (const float*)d_in[2];
    const int*   pT     = (n_in > 3) ? (const int*)d_in[3] : nullptr;
    const int*   pK     = (n_in > 4) ? (const int*)d_in[4] : nullptr;
    int N = in_sizes[1];

    k_init_hist<<<NB, CHUNK>>>(scores, mask, N);
    k_scatter<<<NB, 1024>>>(0, 1, N);   // A -> B
    k_scatter<<<NB, 1024>>>(1, 0, N);   // B -> A
    k_scatter<<<NB, 1024>>>(2, 1, N);   // A -> B
    k_scatter<<<NB, 1024>>>(3, 0, N);   // B -> A  (sorted in g_bufA)
    k_greedy<<<1, NT>>>(spans, scores, pT, pK, N, (float*)d_out, out_size);
}

// round 12
// speedup vs baseline: 1.4085x; 1.4085x over previous
#include <cuda_runtime.h>
#include <stdint.h>
#include <limits.h>

// Problem scale (dataset fixed: T=2048, W=30, N=61440, k=819)
#define NMAX  61440
#define TMAX  2048
#define NB    60          // radix blocks; NB*CHUNK >= NMAX
#define CHUNK 1024
#define NT    1024

#define ST_UND 0
#define ST_ACC 1
#define ST_REJ 2

// ---- device-global scratch (no allocations allowed) ----
__device__ unsigned long long g_bufA[NMAX];
__device__ unsigned long long g_bufB[NMAX];
__device__ unsigned int       g_hist4[4][256 * NB];
__device__ unsigned int       g_base[NB * 256];   // per-pass [block][digit] bases

__device__ __forceinline__ bool spans_cross(int s1, int e1, int s2, int e2) {
    return (s1 < s2 && s2 <= e1 && e1 < e2) || (s2 < s1 && s1 <= e2 && e2 < e1);
}

// ============================================================
// Kernel 1: keys + pass-0 histogram + zero later-pass histograms.
// key64 = (~sortable_asc(score+log m)) << 32 | idx
// ============================================================
__global__ void __launch_bounds__(CHUNK, 1)
k_init_hist(const float* __restrict__ scores, const float* __restrict__ maskp, int N) {
    __shared__ unsigned h[256];
    int t = threadIdx.x, ln = t & 31;
    unsigned ltm = (1u << ln) - 1u;
    if (t < 256) h[t] = 0;
    __syncthreads();

    int i = blockIdx.x * CHUNK + t;
    bool ok = (i < N);
    unsigned d = 256u + (unsigned)ln;
    if (ok) {
        float key = scores[i] + logf(maskp[i]);
        unsigned b   = __float_as_uint(key);
        unsigned asc = (b & 0x80000000u) ? ~b : (b | 0x80000000u);
        unsigned long long k = ((unsigned long long)(~asc) << 32) | (unsigned)i;
        g_bufA[i] = k;
        d = (unsigned)((k >> 32) & 255u);
    }
    unsigned mm = __match_any_sync(0xFFFFFFFFu, d);
    if (ok && (mm & ltm) == 0u) atomicAdd(&h[d], (unsigned)__popc(mm));
    __syncthreads();

    if (t < 256) {
        g_hist4[0][t * NB + blockIdx.x] = h[t];
        g_hist4[1][t * NB + blockIdx.x] = 0;
        g_hist4[2][t * NB + blockIdx.x] = 0;
        g_hist4[3][t * NB + blockIdx.x] = 0;
    }
}

// ============================================================
// Scan pass p: per-(block,digit) scatter bases into g_base[block*256+digit].
// base = scan(digit totals) + prefix of this digit over earlier blocks.
// ============================================================
__global__ void __launch_bounds__(256, 1)
k_scan(int p) {
    __shared__ unsigned tmp8[8];
    int t = threadIdx.x, wp = t >> 5, ln = t & 31;
    const unsigned FULL = 0xFFFFFFFFu;
    const unsigned* hp = &g_hist4[p][t * NB];

    unsigned tot = 0;
    #pragma unroll
    for (int b = 0; b < NB; b++) tot += __ldg(&hp[b]);

    // block exclusive scan of per-digit totals
    unsigned x = tot;
    #pragma unroll
    for (int o = 1; o < 32; o <<= 1) {
        unsigned y = __shfl_up_sync(FULL, x, o);
        if (ln >= o) x += y;
    }
    if (ln == 31) tmp8[wp] = x;
    __syncthreads();
    unsigned add = 0;
    #pragma unroll
    for (int w = 0; w < 8; w++) add += (w < wp) ? tmp8[w] : 0u;

    unsigned run = (x - tot) + add;
    #pragma unroll
    for (int b = 0; b < NB; b++) {
        unsigned c = __ldg(&hp[b]);
        g_base[b * 256 + t] = run;     // coalesced across t per b
        run += c;
    }
}

// ============================================================
// Scatter pass p: 1024 threads, one wave, bases preloaded from g_base.
// Stable match-rank scatter; feeds next pass's per-dest-block hist (p<3).
// ============================================================
__global__ void __launch_bounds__(1024, 1)
k_scatter(int p, int srcIsA, int N) {
    const unsigned long long* src = srcIsA ? g_bufA : g_bufB;
    unsigned long long*       dst = srcIsA ? g_bufB : g_bufA;
    int shift  = 32 + 8 * p;
    int shift2 = shift + 8;

    __shared__ unsigned baseS[256];
    __shared__ unsigned wh[32][257];   // padded: column scan rotates banks
    int t  = threadIdx.x;
    int wp = t >> 5, ln = t & 31;
    unsigned ltm = (1u << ln) - 1u;
    const unsigned FULL = 0xFFFFFFFFu;

    #pragma unroll
    for (int j = t; j < 32 * 257; j += 1024) ((unsigned*)wh)[j] = 0;
    if (t < 256) baseS[t] = __ldg(&g_base[blockIdx.x * 256 + t]);
    __syncthreads();   // *** zeroing must complete before leader count writes ***

    int i = blockIdx.x * 1024 + t;
    bool ok = (i < N);
    unsigned long long v = ok ? src[i] : 0ull;
    unsigned d = ok ? (unsigned)((v >> shift) & 255u) : (256u + (unsigned)ln);
    unsigned mm = __match_any_sync(FULL, d);
    int lr = __popc(mm & ltm);
    if (ok && lr == 0) wh[wp][d] = (unsigned)__popc(mm);
    __syncthreads();

    if (t < 256) {                      // thread t owns digit t
        unsigned run = baseS[t];
        #pragma unroll
        for (int w = 0; w < 32; w++) { unsigned c = wh[w][t]; wh[w][t] = run; run += c; }
    }
    __syncthreads();

    if (ok) {
        unsigned q = wh[wp][d] + (unsigned)lr;
        dst[q] = v;                                  // stable scatter
        if (p < 3) {
            unsigned d2 = (unsigned)((v >> shift2) & 255u);
            atomicAdd(&g_hist4[p + 1][d2 * NB + (q >> 10)], 1u);
        }
    }
}

// ============================================================
// Greedy non-crossing selection: block-parallel fixed-point per chunk.
//   Prefilter: width-0 -> ACC (can never cross); reject vs tables (final).
//   Rounds (full rescan each round): undecided t scans earlier survivors in
//   3 start-buckets; cross ACC -> reject; cross UND -> wait.
// Finalize: first K accepts (candidate order), bitonic by (s*T+e, idx), emit.
// ============================================================
__global__ void __launch_bounds__(NT, 1)
k_greedy(const int* __restrict__ spans, const float* __restrict__ scores,
         const int* __restrict__ pT, const int* __restrict__ pK,
         int N, float* __restrict__ out, int out_size) {
    __shared__ int s2e[TMAX];                 // start -> max end   (-1 unset)
    __shared__ int e2s[TMAX];                 // end   -> min start (INT_MAX unset)
    __shared__ int seC[NT];
    __shared__ int cC[NT];
    __shared__ int stateA[NT];
    __shared__ short bEntries[NT];
    __shared__ int bCnt[64], bOff[64], bFill[64];
    __shared__ int wCnt[32], wOff[32];
    __shared__ unsigned long long accList[2048];
    __shared__ int sh_cnt, sh_done;

    const unsigned FULL = 0xFFFFFFFFu;
    int t = threadIdx.x, wp = t >> 5, ln = t & 31;
    unsigned ltm = (1u << ln) - 1u;

    for (int i = t; i < TMAX; i += NT) { s2e[i] = -1; e2s[i] = INT_MAX; }
    if (t == 0) { sh_cnt = 0; sh_done = 0; }
    __syncthreads();

    int T = pT ? pT[0] : TMAX;
    int K = pK ? pK[0] : 819;
    int k_out = out_size / 5;                  // scores,k | idx,k | spans,2k | valid,k
    if (K > NT) K = NT;
    int nch = (N + NT - 1) / NT;

    for (int ch = 0; ch < nch; ch++) {
        if (sh_done) break;
        int cnt0 = sh_cnt;
        int i = ch * NT + t;
        int myState = ST_REJ;
        int s1 = 0, e1 = 0, c1 = 0;
        if (i < N) {
            c1 = (int)(unsigned)(g_bufA[i] & 0xFFFFFFFFull);
            s1 = __ldg(&spans[2 * c1]);
            e1 = __ldg(&spans[2 * c1 + 1]);
            if (s1 == e1) {
                myState = ST_ACC;              // width-0: can never cross
            } else if (cnt0 == 0) {
                myState = ST_UND;
            } else {
                bool cross = false;
                int w = e1 - s1;
                for (int d = 1; d <= w; d++) cross |= (s2e[s1 + d] > e1);
                for (int d = 0; d < w; d++)  cross |= (e2s[s1 + d] < s1);
                myState = cross ? ST_REJ : ST_UND;
            }
        }
        seC[t] = (s1 << 12) | e1;
        cC[t]  = c1;
        stateA[t] = myState;
        int myB = s1 >> 5;

        // ---- bucket build over UND only ----
        if (t < 64) bCnt[t] = 0;
        __syncthreads();
        if (myState == ST_UND) atomicAdd(&bCnt[myB], 1);
        __syncthreads();
        if (t == 0) {
            int run = 0;
            #pragma unroll
            for (int b = 0; b < 64; b++) { bOff[b] = run; bFill[b] = run; run += bCnt[b]; }
        }
        __syncthreads();
        if (myState == ST_UND) {
            int pos = atomicAdd(&bFill[myB], 1);
            bEntries[pos] = (short)t;
        }
        __syncthreads();

        int bLo = (myB > 0) ? myB - 1 : 0;
        int bHi = (myB < 63) ? myB + 1 : 63;
        int lo = bOff[bLo];
        int hi = bOff[bHi] + bCnt[bHi];

        // ---- rounds: full rescan each round (fast rejection propagation) ----
        while (true) {
            int und = __syncthreads_count(myState == ST_UND);
            if (und == 0) break;
            if (myState == ST_UND) {
                bool rejected = false, blocked = false;
                for (int q = lo; q < hi && !rejected; q++) {
                    int j = bEntries[q];
                    if (j >= t) continue;
                    int st = stateA[j];
                    if (st == ST_REJ) continue;
                    int se2 = seC[j];
                    if (spans_cross(s1, e1, se2 >> 12, se2 & 4095)) {
                        if (st == ST_ACC) rejected = true;
                        else blocked = true;
                    }
                }
                if (rejected)      { myState = ST_REJ; stateA[t] = ST_REJ; }
                else if (!blocked) { myState = ST_ACC; stateA[t] = ST_ACC; }
            }
        }

        // ---- accepted: update tables for later chunks ----
        bool accd = (myState == ST_ACC);
        if (accd) {
            atomicMax(&s2e[s1], e1);
            atomicMin(&e2s[e1], s1);
        }

        // ---- ordered compaction of accepts -> accList ----
        unsigned bal = __ballot_sync(FULL, accd);
        if (ln == 0) wCnt[wp] = __popc(bal);
        __syncthreads();
        if (t < 32) {
            int vv = wCnt[t], a2 = vv;
            #pragma unroll
            for (int o = 1; o < 32; o <<= 1) {
                int nb = __shfl_up_sync(FULL, a2, o);
                if (t >= o) a2 += nb;
            }
            wOff[t] = a2 - vv;
            if (t == 31) {
                sh_cnt = cnt0 + a2;
                if (cnt0 + a2 >= K) sh_done = 1;
            }
        }
        __syncthreads();
        if (accd) {
            int pos = cnt0 + wOff[wp] + __popc(bal & ltm);
            if (pos < 2048)
                accList[pos] = ((unsigned long long)(s1 * T + e1) << 17) | (unsigned)c1;
        }
        __syncthreads();
    }

    // ---- finalize: first K accepts, bitonic by (s*T+e, idx), emit ----
    int cnt = sh_cnt;
    if (cnt > K) cnt = K;
    if (t >= cnt) accList[t] = 0xFFFFFFFFFFFFFFFFull;
    __syncthreads();

    for (int ks = 2; ks <= NT; ks <<= 1) {
        for (int j = ks >> 1; j > 0; j >>= 1) {
            int ixj = t ^ j;
            if (ixj > t) {
                bool up = ((t & ks) == 0);
                unsigned long long a = accList[t], b = accList[ixj];
                if ((a > b) == up) { accList[t] = b; accList[ixj] = a; }
            }
            __syncthreads();
        }
    }

    int vcnt = (cnt < k_out) ? cnt : k_out;
    for (int j = t; j < k_out; j += NT) {
        bool valid = (j < vcnt);
        int c  = valid ? (int)(accList[j] & 0x1FFFFull) : 0;
        float sc = valid ? scores[c] : 0.0f;
        int ss = valid ? spans[2 * c] : 0;
        int ee = valid ? spans[2 * c + 1] : 0;
        out[j]                     = sc;
        out[k_out + j]             = valid ? (float)c : 0.0f;
        out[2 * k_out + 2 * j]     = (float)ss;
        out[2 * k_out + 2 * j + 1] = (float)ee;
        out[4 * k_out + j]         = valid ? 1.0f : 0.0f;
    }
}

// ============================================================
// Launch: 10 nodes.
// ============================================================
extern "C" void kernel_launch(void* const* d_in, const int* in_sizes, int n_in,
                              void* d_out, int out_size) {
    const int*   spans  = (const int*)d_in[0];
    const float* scores = (const float*)d_in[1];
    const float* mask   = (const float*)d_in[2];
    const int*   pT     = (n_in > 3) ? (const int*)d_in[3] : nullptr;
    const int*   pK     = (n_in > 4) ? (const int*)d_in[4] : nullptr;
    int N = in_sizes[1];

    k_init_hist<<<NB, CHUNK>>>(scores, mask, N);
    k_scan<<<1, 256>>>(0);
    k_scatter<<<NB, 1024>>>(0, 1, N);   // A -> B
    k_scan<<<1, 256>>>(1);
    k_scatter<<<NB, 1024>>>(1, 0, N);   // B -> A
    k_scan<<<1, 256>>>(2);
    k_scatter<<<NB, 1024>>>(2, 1, N);   // A -> B
    k_scan<<<1, 256>>>(3);
    k_scatter<<<NB, 1024>>>(3, 0, N);   // B -> A  (sorted in g_bufA)
    k_greedy<<<1, NT>>>(spans, scores, pT, pK, N, (float*)d_out, out_size);
}